// round 1
// baseline (speedup 1.0000x reference)
#include <cuda_runtime.h>

#define BB 2
#define TT 50
#define UU 64
#define PP 5111
#define D4 256   // 4U
#define D2 128   // 2U
#define JJ 50    // MLP hidden

// ---- scratch (device globals; no allocation allowed) ----
__device__ float g_zin[BB * TT * D4];   // xt@Wk + bl
__device__ float g_ht [BB * TT * UU];   // LSTM hidden states
__device__ float g_G  [BB * TT * JJ];   // ht @ W1[:64]
__device__ float g_xw1[PP * JJ];        // X @ W1[64:192] + b1

// ============================================================
// Kernel 1: Z_in[b,t,d] = sum_k xt[b,t,k] * Wk[k,d] + bl[d]
//   xt[k] = X[tgt, k mod 128] * emb2[cor, k]
// ============================================================
__global__ void k_zin(const int* __restrict__ tgt, const int* __restrict__ cor,
                      const float* __restrict__ X, const float* __restrict__ emb2,
                      const float* __restrict__ Wk, const float* __restrict__ bl)
{
    int bt = blockIdx.x;      // 0..99
    int d  = threadIdx.x;     // 0..255
    __shared__ float xs[D4];
    int tg = tgt[bt];
    int cr = cor[bt];
    xs[d] = X[tg * D2 + (d & (D2 - 1))] * emb2[cr * D4 + d];
    __syncthreads();
    float z = bl ? bl[d] : 0.f;
    #pragma unroll 8
    for (int k = 0; k < D4; k++)
        z += xs[k] * Wk[k * D4 + d];
    g_zin[bt * D4 + d] = z;
}

// ============================================================
// Kernel 2: LSTM recurrence. One block per batch b, 256 threads.
// Wr column (64 floats) lives in registers per thread.
// ============================================================
__global__ void k_lstm(const float* __restrict__ Wr)
{
    int b = blockIdx.x;
    int d = threadIdx.x;      // 0..255
    float wr[UU];
    #pragma unroll
    for (int u = 0; u < UU; u++)
        wr[u] = Wr[u * D4 + d];         // coalesced

    __shared__ float hs[UU];
    __shared__ float zs[D4];
    float creg = 0.f;
    if (d < UU) hs[d] = 0.f;
    __syncthreads();

    for (int t = 0; t < TT; t++) {
        float z = g_zin[(b * TT + t) * D4 + d];
        #pragma unroll
        for (int u = 0; u < UU; u++)
            z += hs[u] * wr[u];
        zs[d] = z;
        __syncthreads();
        if (d < UU) {
            float gi = 1.f / (1.f + expf(-zs[d]));
            float gf = 1.f / (1.f + expf(-zs[UU + d]));
            float gg = tanhf(zs[2 * UU + d]);
            float go = 1.f / (1.f + expf(-zs[3 * UU + d]));
            creg = gf * creg + gi * gg;
            float h = go * tanhf(creg);
            hs[d] = h;
            g_ht[(b * TT + t) * UU + d] = h;
        }
        __syncthreads();
    }
}

// ============================================================
// Kernel 3: G[b,t,j] = sum_u ht[b,t,u] * W1[u,j]
// ============================================================
__global__ void k_G(const float* __restrict__ W1)
{
    int bt = blockIdx.x;      // 0..99
    int j  = threadIdx.x;     // 0..63
    __shared__ float hsh[UU];
    if (j < UU) hsh[j] = g_ht[bt * UU + j];
    __syncthreads();
    if (j < JJ) {
        float s = 0.f;
        #pragma unroll
        for (int u = 0; u < UU; u++)
            s += hsh[u] * W1[u * JJ + j];
        g_G[bt * JJ + j] = s;
    }
}

// ============================================================
// Kernel 4: XW1[p,j] = sum_k X[p,k] * W1[64+k, j] + b1[j]
// ============================================================
__global__ void k_xw1(const float* __restrict__ X, const float* __restrict__ W1,
                      const float* __restrict__ b1)
{
    int p = blockIdx.x;       // 0..P-1
    int j = threadIdx.x;      // 0..63
    __shared__ float xs[D2];
    xs[j]      = X[p * D2 + j];
    xs[j + 64] = X[p * D2 + j + 64];
    __syncthreads();
    if (j < JJ) {
        float s = b1 ? b1[j] : 0.f;
        #pragma unroll 8
        for (int k = 0; k < D2; k++)
            s += xs[k] * W1[(UU + k) * JJ + j];
        g_xw1[p * JJ + j] = s;
    }
}

// ============================================================
// Kernel 5 (main): one warp per (b,p).
//   acc[j] suffix-accumulates a[b,s,p]*G[b,s,j] for s = T-1..0,
//   out[b,s,p] = sum_j relu(acc[j] + XW1[p,j]) * W2[j] + b2
// Lane l owns j = l and j = l+32 (latter valid if < 50).
// ============================================================
__global__ void k_main(const int* __restrict__ tgt, const float* __restrict__ cosX,
                       const float* __restrict__ W2, const float* __restrict__ b2,
                       float* __restrict__ out)
{
    __shared__ float Gs[BB * TT * JJ];   // 20 KB
    __shared__ int   tg[BB * TT];
    int tid = threadIdx.x;
    for (int i = tid; i < BB * TT * JJ; i += blockDim.x) Gs[i] = g_G[i];
    if (tid < BB * TT) tg[tid] = tgt[tid];
    __syncthreads();

    int gw = blockIdx.x * (blockDim.x >> 5) + (tid >> 5);
    if (gw >= BB * PP) return;
    int b = gw / PP;
    int p = gw - b * PP;
    int l = tid & 31;
    int j1 = l + 32;
    bool v1 = (j1 < JJ);

    float xw0 = g_xw1[p * JJ + l];
    float xw1 = v1 ? g_xw1[p * JJ + j1] : 0.f;
    float w20 = W2[l];
    float w21 = v1 ? W2[j1] : 0.f;
    float bias2 = b2 ? b2[0] : 0.f;

    float acc0 = 0.f, acc1 = 0.f;

    // prefetch first gather
    float a = __ldg(&cosX[(size_t)tg[b * TT + (TT - 1)] * PP + p]);

    for (int s = TT - 1; s >= 0; s--) {
        float a_next = 0.f;
        if (s > 0)
            a_next = __ldg(&cosX[(size_t)tg[b * TT + s - 1] * PP + p]);

        int go = (b * TT + s) * JJ;
        acc0 += a * Gs[go + l];
        float g1 = v1 ? Gs[go + j1] : 0.f;
        acc1 += a * g1;

        float z0 = fmaxf(acc0 + xw0, 0.f);
        float z1 = fmaxf(acc1 + xw1, 0.f);
        float part = z0 * w20 + z1 * w21;
        #pragma unroll
        for (int off = 16; off > 0; off >>= 1)
            part += __shfl_xor_sync(0xffffffffu, part, off);
        if (l == 0)
            out[(b * TT + s) * PP + p] = part + bias2;

        a = a_next;
    }
}

// ============================================================
// Launcher
// ============================================================
extern "C" void kernel_launch(void* const* d_in, const int* in_sizes, int n_in,
                              void* d_out, int out_size)
{
    const int   *tgt = nullptr, *cor = nullptr;
    const float *X = nullptr, *cosX = nullptr, *emb2 = nullptr, *Wk = nullptr;
    const float *Wr = nullptr, *bl = nullptr, *W1 = nullptr, *b1 = nullptr;
    const float *W2 = nullptr, *b2 = nullptr;

    int cnt1 = 0;
    for (int i = 0; i < n_in; i++) if (in_sizes[i] == 1) cnt1++;
    int seen1 = 0;

    for (int i = 0; i < n_in; i++) {
        int sz = in_sizes[i];
        const void* ptr = d_in[i];
        if (sz == BB * TT) {                       // 100: data_target then data_cor
            if (!tgt) tgt = (const int*)ptr; else cor = (const int*)ptr;
        } else if (sz == PP * PP)   cosX = (const float*)ptr;
        else if (sz == PP * D2)     X    = (const float*)ptr;
        else if (sz == D4 * D4)     Wk   = (const float*)ptr;
        else if (sz == UU * D4)     Wr   = (const float*)ptr;
        else if (sz == 2 * D4)      emb2 = (const float*)ptr;
        else if (sz == D4)          bl   = (const float*)ptr;
        else if (sz == 3 * UU * JJ) W1   = (const float*)ptr;
        else if (sz == JJ) {                       // 50: b1 then W2 (dict order)
            if (!b1) b1 = (const float*)ptr; else W2 = (const float*)ptr;
        } else if (sz == 1) {                      // num_pro (maybe) then b2: take last
            seen1++;
            if (seen1 == cnt1) b2 = (const float*)ptr;
        }
        // trimatrix (2500) not needed: suffix-sum is done analytically
    }

    // 1) hoisted input projection
    k_zin<<<BB * TT, D4>>>(tgt, cor, X, emb2, Wk, bl);
    // 2) sequential LSTM recurrence
    k_lstm<<<BB, D4>>>(Wr);
    // 3) G = ht @ W1[:64]
    k_G<<<BB * TT, 64>>>(W1);
    // 4) XW1 = X @ W1[64:192] + b1 (independent of 1-3)
    k_xw1<<<PP, 64>>>(X, W1, b1);
    // 5) fused suffix-sum + MLP + reduce
    int warps_per_block = 256 / 32;
    int nblk = (BB * PP + warps_per_block - 1) / warps_per_block;
    k_main<<<nblk, 256>>>(tgt, cosX, W2, b2, (float*)d_out);
}

// round 2
// speedup vs baseline: 1.2785x; 1.2785x over previous
#include <cuda_runtime.h>

#define BB 2
#define TT 50
#define UU 64
#define PP 5111
#define D4 256   // 4U
#define D2 128   // 2U
#define JJ 50    // MLP hidden

// ---- scratch (device globals; no allocation allowed) ----
__device__ float g_zin[BB * TT * D4];   // xt@Wk + bl
__device__ float g_G  [BB * TT * JJ];   // ht @ W1[:64]
__device__ float g_xw1[PP * JJ];        // X @ W1[64:192] + b1

__device__ __forceinline__ float fast_sigmoid(float x) {
    return __fdividef(1.0f, 1.0f + __expf(-x));
}
__device__ __forceinline__ float fast_tanh(float x) {
    float r;
    asm("tanh.approx.f32 %0, %1;" : "=f"(r) : "f"(x));
    return r;
}

// ============================================================
// Kernel 1: Z_in[b,t,d] = sum_k xt[b,t,k] * Wk[k,d] + bl[d]
//   xt[k] = X[tgt, k mod 128] * emb2[cor, k]
// grid (25, 4): x = group of 4 bt, y = 64-wide d chunk.
// block 256 = 64 d_local x 4 k-splits.
// ============================================================
__global__ void k_zin(const int* __restrict__ tgt, const int* __restrict__ cor,
                      const float* __restrict__ X, const float* __restrict__ emb2,
                      const float* __restrict__ Wk, const float* __restrict__ bl)
{
    __shared__ float xs[4][D4];          // 4 bt rows
    __shared__ float zp[4][4][UU];       // [bt][ks][d_local]
    int tid = threadIdx.x;
    int dl  = tid & 63;
    int ks  = tid >> 6;                  // 0..3
    int d   = blockIdx.y * 64 + dl;
    int bt0 = blockIdx.x * 4;

    // stage xt for the 4 bt rows
    for (int i = tid; i < 4 * D4; i += 256) {
        int bl_ = i >> 8;                // bt local
        int k   = i & (D4 - 1);
        int bt  = bt0 + bl_;
        int tg  = tgt[bt];
        int cr  = cor[bt];
        xs[bl_][k] = X[tg * D2 + (k & (D2 - 1))] * emb2[cr * D4 + k];
    }
    __syncthreads();

    float a0 = 0.f, a1 = 0.f, a2 = 0.f, a3 = 0.f;
    int k0 = ks * 64;
    #pragma unroll 8
    for (int k = k0; k < k0 + 64; k++) {
        float w = Wk[k * D4 + d];
        a0 += xs[0][k] * w;
        a1 += xs[1][k] * w;
        a2 += xs[2][k] * w;
        a3 += xs[3][k] * w;
    }
    zp[0][ks][dl] = a0;
    zp[1][ks][dl] = a1;
    zp[2][ks][dl] = a2;
    zp[3][ks][dl] = a3;
    __syncthreads();

    if (ks == 0) {
        float bv = bl[d];
        #pragma unroll
        for (int bl_ = 0; bl_ < 4; bl_++) {
            float z = zp[bl_][0][dl] + zp[bl_][1][dl] + zp[bl_][2][dl] + zp[bl_][3][dl] + bv;
            g_zin[(bt0 + bl_) * D4 + d] = z;
        }
    }
}

// ============================================================
// Kernel 2: LSTM recurrence + fused G = ht @ W1[:64].
// One block per batch b, 256 threads. Wr column in registers.
// ht history kept in smem; G written to global.
// ============================================================
__global__ void k_lstm(const float* __restrict__ Wr, const float* __restrict__ W1)
{
    int b = blockIdx.x;
    int d = threadIdx.x;      // 0..255
    float wr[UU];
    #pragma unroll
    for (int u = 0; u < UU; u++)
        wr[u] = Wr[u * D4 + d];         // coalesced

    __shared__ float hts[TT + 1][UU];   // hts[t+1] = h_t ; row 0 = zeros
    __shared__ float zs[D4];
    __shared__ float w1s[UU * JJ];      // W1[:64] staged

    // stage W1a while recurrence warms up is not possible (sync), do it now
    for (int i = d; i < UU * JJ; i += 256) w1s[i] = W1[i];

    float creg = 0.f;
    if (d < UU) hts[0][d] = 0.f;
    __syncthreads();

    for (int t = 0; t < TT; t++) {
        float z = g_zin[(b * TT + t) * D4 + d];
        const float* h = hts[t];
        float a0 = 0.f, a1 = 0.f, a2 = 0.f, a3 = 0.f;
        #pragma unroll
        for (int u = 0; u < UU; u += 4) {
            a0 += h[u]     * wr[u];
            a1 += h[u + 1] * wr[u + 1];
            a2 += h[u + 2] * wr[u + 2];
            a3 += h[u + 3] * wr[u + 3];
        }
        zs[d] = z + (a0 + a1) + (a2 + a3);
        __syncthreads();
        if (d < UU) {
            float gi = fast_sigmoid(zs[d]);
            float gf = fast_sigmoid(zs[UU + d]);
            float gg = fast_tanh(zs[2 * UU + d]);
            float go = fast_sigmoid(zs[3 * UU + d]);
            creg = gf * creg + gi * gg;
            hts[t + 1][d] = go * fast_tanh(creg);
        }
        __syncthreads();
    }

    // fused: G[b,t,j] = sum_u h_t[u] * W1[u,j]
    for (int idx = d; idx < TT * JJ; idx += 256) {
        int t = idx / JJ;
        int j = idx - t * JJ;
        const float* h = hts[t + 1];
        float s0 = 0.f, s1 = 0.f;
        #pragma unroll
        for (int u = 0; u < UU; u += 2) {
            s0 += h[u]     * w1s[u * JJ + j];
            s1 += h[u + 1] * w1s[(u + 1) * JJ + j];
        }
        g_G[(b * TT + t) * JJ + j] = s0 + s1;
    }
}

// ============================================================
// Kernel 3: XW1[p,j] = sum_k X[p,k] * W1[64+k, j] + b1[j]
// 256-thread block = 8 warps, warp w handles p = blk*8 + w.
// W1b staged once per block in smem.
// ============================================================
__global__ void k_xw1(const float* __restrict__ X, const float* __restrict__ W1,
                      const float* __restrict__ b1)
{
    __shared__ float w1s[D2 * JJ + 16]; // 6400 + pad
    __shared__ float xsm[8][D2];
    int tid = threadIdx.x;
    // W1 rows 64..191 are contiguous starting at W1 + 64*50
    for (int i = tid; i < D2 * JJ; i += 256) w1s[i] = W1[UU * JJ + i];
    if (tid < 16) w1s[D2 * JJ + tid] = 0.f;
    int p0 = blockIdx.x * 8;
    for (int i = tid; i < 8 * D2; i += 256) {
        int pl = i >> 7;
        int k  = i & (D2 - 1);
        int p  = p0 + pl;
        xsm[pl][k] = (p < PP) ? X[p * D2 + k] : 0.f;
    }
    __syncthreads();

    int w = tid >> 5;
    int l = tid & 31;
    int p = p0 + w;
    if (p >= PP) return;
    int j1 = l + 32;
    bool v1 = (j1 < JJ);

    float s0 = b1[l];
    float s1 = v1 ? b1[j1] : 0.f;
    #pragma unroll 4
    for (int k = 0; k < D2; k++) {
        float x = xsm[w][k];
        s0 += x * w1s[k * JJ + l];
        s1 += x * w1s[k * JJ + j1];   // pad-safe, zeroed
    }
    g_xw1[p * JJ + l] = s0;
    if (v1) g_xw1[p * JJ + j1] = s1;
}

// ============================================================
// Kernel 4 (main): 4 threads per (b,p) quad; lane%4 = q owns
// j in [13q, 13q+13) (q=3 owns 11). Suffix-recurrence over s:
//   acc[j] += a[b,s,p] * G[b,s,j]
//   out[b,s,p] = sum_j relu(acc[j]+XW1[p,j]) * W2[j] + b2
// Quad-reduce via 2 shfl.
// ============================================================
__global__ void k_main(const int* __restrict__ tgt, const float* __restrict__ cosX,
                       const float* __restrict__ W2, const float* __restrict__ b2,
                       float* __restrict__ out)
{
    __shared__ float Gs[BB * TT * JJ + 16];   // 20 KB + pad
    __shared__ int   tg[BB * TT];
    int tid = threadIdx.x;
    for (int i = tid; i < BB * TT * JJ; i += blockDim.x) Gs[i] = g_G[i];
    if (tid < 16) Gs[BB * TT * JJ + tid] = 0.f;
    if (tid < BB * TT) tg[tid] = tgt[tid];
    __syncthreads();

    int quad = (blockIdx.x * blockDim.x + tid) >> 2;
    if (quad >= BB * PP) return;
    int b = quad / PP;
    int p = quad - b * PP;
    int q = tid & 3;
    int jb = q * 13;

    float accr[13], xwr[13], w2r[13];
    #pragma unroll
    for (int m = 0; m < 13; m++) {
        int j = jb + m;
        bool v = (j < JJ);
        accr[m] = 0.f;
        xwr[m]  = v ? g_xw1[p * JJ + j] : 0.f;
        w2r[m]  = v ? W2[j] : 0.f;
    }
    float bias2 = b2[0];

    // prefetch first gather
    float a = __ldg(&cosX[(size_t)tg[b * TT + (TT - 1)] * PP + p]);

    #pragma unroll 2
    for (int s = TT - 1; s >= 0; s--) {
        float a_next = (s > 0)
            ? __ldg(&cosX[(size_t)tg[b * TT + s - 1] * PP + p]) : 0.f;

        int go = (b * TT + s) * JJ + jb;
        float part = 0.f;
        #pragma unroll
        for (int m = 0; m < 13; m++) {
            accr[m] += a * Gs[go + m];            // pad-safe (zeroed)
            float z = fmaxf(accr[m] + xwr[m], 0.f);
            part += z * w2r[m];                   // w2r=0 masks j>=50
        }
        part += __shfl_xor_sync(0xffffffffu, part, 1);
        part += __shfl_xor_sync(0xffffffffu, part, 2);
        if (q == 0)
            out[(b * TT + s) * PP + p] = part + bias2;

        a = a_next;
    }
}

// ============================================================
// Launcher
// ============================================================
extern "C" void kernel_launch(void* const* d_in, const int* in_sizes, int n_in,
                              void* d_out, int out_size)
{
    const int   *tgt = nullptr, *cor = nullptr;
    const float *X = nullptr, *cosX = nullptr, *emb2 = nullptr, *Wk = nullptr;
    const float *Wr = nullptr, *bl = nullptr, *W1 = nullptr, *b1 = nullptr;
    const float *W2 = nullptr, *b2 = nullptr;

    int cnt1 = 0;
    for (int i = 0; i < n_in; i++) if (in_sizes[i] == 1) cnt1++;
    int seen1 = 0;

    for (int i = 0; i < n_in; i++) {
        int sz = in_sizes[i];
        const void* ptr = d_in[i];
        if (sz == BB * TT) {                       // 100: data_target then data_cor
            if (!tgt) tgt = (const int*)ptr; else cor = (const int*)ptr;
        } else if (sz == PP * PP)   cosX = (const float*)ptr;
        else if (sz == PP * D2)     X    = (const float*)ptr;
        else if (sz == D4 * D4)     Wk   = (const float*)ptr;
        else if (sz == UU * D4)     Wr   = (const float*)ptr;
        else if (sz == 2 * D4)      emb2 = (const float*)ptr;
        else if (sz == D4)          bl   = (const float*)ptr;
        else if (sz == 3 * UU * JJ) W1   = (const float*)ptr;
        else if (sz == JJ) {                       // 50: b1 then W2 (dict order)
            if (!b1) b1 = (const float*)ptr; else W2 = (const float*)ptr;
        } else if (sz == 1) {                      // num_pro (maybe) then b2: take last
            seen1++;
            if (seen1 == cnt1) b2 = (const float*)ptr;
        }
        // trimatrix (2500) not needed: suffix-sum is done analytically
    }

    // 1) hoisted input projection (Wk traffic amortized over 4 bt, 4-way k split)
    k_zin<<<dim3(25, 4), 256>>>(tgt, cor, X, emb2, Wk, bl);
    // 2) sequential LSTM recurrence + fused G projection
    k_lstm<<<BB, D4>>>(Wr, W1);
    // 3) XW1 = X @ W1[64:192] + b1 (independent of 1-2)
    k_xw1<<<(PP + 7) / 8, 256>>>(X, W1, b1);
    // 4) fused suffix-sum + MLP + quad reduce
    int nthreads = 4 * BB * PP;                    // 40888
    int nblk = (nthreads + 255) / 256;             // 160
    k_main<<<nblk, 256>>>(tgt, cosX, W2, b2, (float*)d_out);
}

// round 3
// speedup vs baseline: 1.6531x; 1.2930x over previous
#include <cuda_runtime.h>

#define BB 2
#define TT 50
#define UU 64
#define PP 5111
#define D4 256   // 4U
#define D2 128   // 2U
#define JJ 50    // MLP hidden
#define SCH 25   // s per chunk (2 chunks)

// ---- scratch (device globals; no allocation allowed) ----
__device__ float g_zin[BB * TT * D4];   // xt@Wk + bl
__device__ float g_G  [BB * TT * JJ];   // ht @ W1[:64]
__device__ float g_xw1[PP * JJ];        // X @ W1[64:192] + b1

__device__ __forceinline__ float fast_tanh(float x) {
    float r;
    asm("tanh.approx.f32 %0, %1;" : "=f"(r) : "f"(x));
    return r;
}
__device__ __forceinline__ float fast_sigmoid(float x) {
    return fmaf(fast_tanh(0.5f * x), 0.5f, 0.5f);
}

// ============================================================
// Kernel 1 (fused prep): blocks [0,100) compute Z_in, blocks
// [100, 100+639) compute XW1. Independent work, one launch.
//
// zin role: Z_in[b,t,d] = sum_k xt[k]*Wk[k,d] + bl[d],
//   xt[k] = X[tgt, k mod 128] * emb2[cor, k]
//   virtual grid (25 groups of 4 bt) x (4 d-chunks of 64).
// xw1 role: XW1[p,j] = sum_k X[p,k]*W1[64+k,j] + b1[j],
//   8 p per block, W1b staged in smem.
// ============================================================
__global__ void k_prep(const int* __restrict__ tgt, const int* __restrict__ cor,
                       const float* __restrict__ X, const float* __restrict__ emb2,
                       const float* __restrict__ Wk, const float* __restrict__ bl,
                       const float* __restrict__ W1, const float* __restrict__ b1)
{
    __shared__ float sbuf[7440];   // max(zin: 2048, xw1: 7440) floats
    int tid = threadIdx.x;

    if (blockIdx.x < 100) {
        // ---------------- zin role ----------------
        float* xs = sbuf;                 // [4][D4]
        float* zp = sbuf + 4 * D4;        // [4][4][UU]
        int zb  = blockIdx.x;
        int grp = zb >> 2;                // 0..24
        int ych = zb & 3;                 // 0..3
        int dl  = tid & 63;
        int ks  = tid >> 6;               // 0..3
        int d   = ych * 64 + dl;
        int bt0 = grp * 4;

        for (int i = tid; i < 4 * D4; i += 256) {
            int bl_ = i >> 8;
            int k   = i & (D4 - 1);
            int bt  = bt0 + bl_;
            int tg  = tgt[bt];
            int cr  = cor[bt];
            xs[bl_ * D4 + k] = X[tg * D2 + (k & (D2 - 1))] * emb2[cr * D4 + k];
        }
        __syncthreads();

        float a0 = 0.f, a1 = 0.f, a2 = 0.f, a3 = 0.f;
        int k0 = ks * 64;
        #pragma unroll 8
        for (int k = k0; k < k0 + 64; k++) {
            float w = Wk[k * D4 + d];
            a0 += xs[0 * D4 + k] * w;
            a1 += xs[1 * D4 + k] * w;
            a2 += xs[2 * D4 + k] * w;
            a3 += xs[3 * D4 + k] * w;
        }
        zp[(0 * 4 + ks) * UU + dl] = a0;
        zp[(1 * 4 + ks) * UU + dl] = a1;
        zp[(2 * 4 + ks) * UU + dl] = a2;
        zp[(3 * 4 + ks) * UU + dl] = a3;
        __syncthreads();

        if (ks == 0) {
            float bv = bl[d];
            #pragma unroll
            for (int bl_ = 0; bl_ < 4; bl_++) {
                float z = zp[(bl_ * 4 + 0) * UU + dl] + zp[(bl_ * 4 + 1) * UU + dl]
                        + zp[(bl_ * 4 + 2) * UU + dl] + zp[(bl_ * 4 + 3) * UU + dl] + bv;
                g_zin[(bt0 + bl_) * D4 + d] = z;
            }
        }
    } else {
        // ---------------- xw1 role ----------------
        float* w1s = sbuf;                 // D2*JJ + 16
        float* xsm = sbuf + D2 * JJ + 16;  // [8][D2]
        for (int i = tid; i < D2 * JJ; i += 256) w1s[i] = W1[UU * JJ + i];
        if (tid < 16) w1s[D2 * JJ + tid] = 0.f;
        int p0 = (blockIdx.x - 100) * 8;
        for (int i = tid; i < 8 * D2; i += 256) {
            int pl = i >> 7;
            int k  = i & (D2 - 1);
            int p  = p0 + pl;
            xsm[pl * D2 + k] = (p < PP) ? X[p * D2 + k] : 0.f;
        }
        __syncthreads();

        int w = tid >> 5;
        int l = tid & 31;
        int p = p0 + w;
        if (p >= PP) return;
        int j1 = l + 32;
        bool v1 = (j1 < JJ);

        float s0 = b1[l];
        float s1 = v1 ? b1[j1] : 0.f;
        #pragma unroll 4
        for (int k = 0; k < D2; k++) {
            float x = xsm[w * D2 + k];
            s0 += x * w1s[k * JJ + l];
            s1 += x * w1s[k * JJ + j1];   // pad-safe
        }
        g_xw1[p * JJ + l] = s0;
        if (v1) g_xw1[p * JJ + j1] = s1;
    }
}

// ============================================================
// Kernel 2: LSTM recurrence + fused G = ht @ W1[:64].
// One block per batch b, 256 threads. Wr column in registers.
// Next-step z prefetched into a register ahead of the barrier.
// ============================================================
__global__ void __launch_bounds__(256, 1)
k_lstm(const float* __restrict__ Wr, const float* __restrict__ W1)
{
    int b = blockIdx.x;
    int d = threadIdx.x;      // 0..255
    float wr[UU];
    #pragma unroll
    for (int u = 0; u < UU; u++)
        wr[u] = Wr[u * D4 + d];         // coalesced

    __shared__ float hts[TT + 1][UU];   // hts[t+1] = h_t ; row 0 = zeros
    __shared__ float zs[D4];
    __shared__ float w1s[UU * JJ];      // W1[:64] staged

    for (int i = d; i < UU * JJ; i += 256) w1s[i] = W1[i];

    float creg = 0.f;
    if (d < UU) hts[0][d] = 0.f;

    float znext = g_zin[(b * TT) * D4 + d];   // prefetch t=0
    __syncthreads();

    for (int t = 0; t < TT; t++) {
        float z = znext;
        // issue next prefetch early; completes during gate phase
        if (t < TT - 1)
            znext = g_zin[(b * TT + t + 1) * D4 + d];

        const float* h = hts[t];
        float a0 = 0.f, a1 = 0.f, a2 = 0.f, a3 = 0.f;
        float a4 = 0.f, a5 = 0.f, a6 = 0.f, a7 = 0.f;
        #pragma unroll
        for (int u = 0; u < UU; u += 8) {
            a0 += h[u]     * wr[u];
            a1 += h[u + 1] * wr[u + 1];
            a2 += h[u + 2] * wr[u + 2];
            a3 += h[u + 3] * wr[u + 3];
            a4 += h[u + 4] * wr[u + 4];
            a5 += h[u + 5] * wr[u + 5];
            a6 += h[u + 6] * wr[u + 6];
            a7 += h[u + 7] * wr[u + 7];
        }
        zs[d] = z + ((a0 + a1) + (a2 + a3)) + ((a4 + a5) + (a6 + a7));
        __syncthreads();
        if (d < UU) {
            float gi = fast_sigmoid(zs[d]);
            float gf = fast_sigmoid(zs[UU + d]);
            float gg = fast_tanh(zs[2 * UU + d]);
            float go = fast_sigmoid(zs[3 * UU + d]);
            creg = gf * creg + gi * gg;
            hts[t + 1][d] = go * fast_tanh(creg);
        }
        __syncthreads();
    }

    // fused: G[b,t,j] = sum_u h_t[u] * W1[u,j]
    for (int idx = d; idx < TT * JJ; idx += 256) {
        int t = idx / JJ;
        int j = idx - t * JJ;
        const float* h = hts[t + 1];
        float s0 = 0.f, s1 = 0.f;
        #pragma unroll
        for (int u = 0; u < UU; u += 2) {
            s0 += h[u]     * w1s[u * JJ + j];
            s1 += h[u + 1] * w1s[(u + 1) * JJ + j];
        }
        g_G[(b * TT + t) * JJ + j] = s0 + s1;
    }
}

// ============================================================
// Kernel 3 (main): 8 threads per (b,p); lane octet member q owns
// j in [7q, 7q+7) (j>=50 masked via w2=0). blockIdx.y = s-chunk:
//   chunk 1: s in [25,50); chunk 0: accumulate t=49..25 (cheap),
//   then s in [0,25).
//   acc[j] suffix-accumulates a[b,t,p]*G[b,t,j]
//   out[b,s,p] = sum_j relu(acc[j]+XW1[p,j])*W2[j] + b2
// Octet reduce = 3 shfl.
// ============================================================
__global__ void k_main(const int* __restrict__ tgt, const float* __restrict__ cosX,
                       const float* __restrict__ W2, const float* __restrict__ b2,
                       float* __restrict__ out)
{
    __shared__ float Gs[BB * TT * JJ + 64];   // 20 KB + pad (j-overhang safe)
    __shared__ int   tg[BB * TT];
    int tid = threadIdx.x;
    for (int i = tid; i < BB * TT * JJ; i += blockDim.x) Gs[i] = g_G[i];
    if (tid < 64) Gs[BB * TT * JJ + tid] = 0.f;
    if (tid < BB * TT) tg[tid] = tgt[tid];
    __syncthreads();

    int grp = (blockIdx.x * blockDim.x + tid) >> 3;
    if (grp >= BB * PP) return;
    int b = grp / PP;
    int p = grp - b * PP;
    int q = tid & 7;
    int jb = q * 7;
    int ch = blockIdx.y;                  // 0 or 1
    const int s_lo = ch * SCH;
    const int s_hi = s_lo + SCH - 1;      // 24 or 49

    float accr[7], xwr[7], w2r[7];
    #pragma unroll
    for (int m = 0; m < 7; m++) {
        int j = jb + m;
        bool v = (j < JJ);
        accr[m] = 0.f;
        xwr[m]  = v ? g_xw1[p * JJ + j] : 0.f;
        w2r[m]  = v ? W2[j] : 0.f;
    }
    float bias2 = b2[0];

    // phase A (chunk 0 only): accumulate tail t = 49..25, no output
    if (ch == 0) {
        #pragma unroll 5
        for (int t = TT - 1; t > s_hi; t--) {
            float a = __ldg(&cosX[(size_t)tg[b * TT + t] * PP + p]);
            int go = (b * TT + t) * JJ + jb;
            #pragma unroll
            for (int m = 0; m < 7; m++)
                accr[m] += a * Gs[go + m];
        }
    }

    // phase B: s = s_hi .. s_lo with output
    float a = __ldg(&cosX[(size_t)tg[b * TT + s_hi] * PP + p]);
    #pragma unroll 5
    for (int s = s_hi; s >= s_lo; s--) {
        float a_next = (s > s_lo)
            ? __ldg(&cosX[(size_t)tg[b * TT + s - 1] * PP + p]) : 0.f;

        int go = (b * TT + s) * JJ + jb;
        float part = 0.f;
        #pragma unroll
        for (int m = 0; m < 7; m++) {
            accr[m] += a * Gs[go + m];            // pad-safe
            float z = fmaxf(accr[m] + xwr[m], 0.f);
            part += z * w2r[m];                   // w2r=0 masks j>=50
        }
        part += __shfl_xor_sync(0xffffffffu, part, 1);
        part += __shfl_xor_sync(0xffffffffu, part, 2);
        part += __shfl_xor_sync(0xffffffffu, part, 4);
        if (q == 0)
            out[(b * TT + s) * PP + p] = part + bias2;

        a = a_next;
    }
}

// ============================================================
// Launcher
// ============================================================
extern "C" void kernel_launch(void* const* d_in, const int* in_sizes, int n_in,
                              void* d_out, int out_size)
{
    const int   *tgt = nullptr, *cor = nullptr;
    const float *X = nullptr, *cosX = nullptr, *emb2 = nullptr, *Wk = nullptr;
    const float *Wr = nullptr, *bl = nullptr, *W1 = nullptr, *b1 = nullptr;
    const float *W2 = nullptr, *b2 = nullptr;

    int cnt1 = 0;
    for (int i = 0; i < n_in; i++) if (in_sizes[i] == 1) cnt1++;
    int seen1 = 0;

    for (int i = 0; i < n_in; i++) {
        int sz = in_sizes[i];
        const void* ptr = d_in[i];
        if (sz == BB * TT) {                       // 100: data_target then data_cor
            if (!tgt) tgt = (const int*)ptr; else cor = (const int*)ptr;
        } else if (sz == PP * PP)   cosX = (const float*)ptr;
        else if (sz == PP * D2)     X    = (const float*)ptr;
        else if (sz == D4 * D4)     Wk   = (const float*)ptr;
        else if (sz == UU * D4)     Wr   = (const float*)ptr;
        else if (sz == 2 * D4)      emb2 = (const float*)ptr;
        else if (sz == D4)          bl   = (const float*)ptr;
        else if (sz == 3 * UU * JJ) W1   = (const float*)ptr;
        else if (sz == JJ) {                       // 50: b1 then W2 (dict order)
            if (!b1) b1 = (const float*)ptr; else W2 = (const float*)ptr;
        } else if (sz == 1) {                      // num_pro (maybe) then b2: take last
            seen1++;
            if (seen1 == cnt1) b2 = (const float*)ptr;
        }
        // trimatrix (2500) not needed: suffix-sum is done analytically
    }

    // 1) fused input projection + XW1 (independent roles, one wave)
    int nxw1 = (PP + 7) / 8;                       // 639
    k_prep<<<100 + nxw1, 256>>>(tgt, cor, X, emb2, Wk, bl, W1, b1);
    // 2) sequential LSTM recurrence + fused G projection
    k_lstm<<<BB, D4>>>(Wr, W1);
    // 3) fused suffix-sum + MLP + octet reduce, 2 s-chunks
    int nthreads = 8 * BB * PP;                    // 81776
    int nblkx = (nthreads + 255) / 256;            // 320
    k_main<<<dim3(nblkx, 2), 256>>>(tgt, cosX, W2, b2, (float*)d_out);
}